// round 17
// baseline (speedup 1.0000x reference)
#include <cuda_runtime.h>
#include <cuda_fp16.h>
#include <cstdint>

// ============================================================================
// All-HMMA pipeline, plain fp16 GEMMs, 3-stage cp.async, N-major grid (L2 A-reuse).
// LN1 -> QKV GEMM -> attention+LN2 -> FFN1 GEMM -> FFN2 GEMM
// B=8192, T=8, C=512, H=8, HS=64, FF=2048.  M_total = 65536 rows.
// ============================================================================

#define Cd 512
#define Td 8
#define Hd 8
#define HSd 64
#define FFd 2048
#define NQKV 1536
#define MTOT 65536

// ---- device scratch ----
__device__ __half g_xn[(size_t)MTOT * Cd];
__device__ __half g_pkv[(size_t)MTOT * NQKV];
__device__ __half g_h[(size_t)MTOT * Cd];
__device__ __half g_a[(size_t)MTOT * FFd];
__device__ __half g_w1t[FFd * Cd];
__device__ __half g_w2t[Cd * FFd];
__device__ __half g_wqkvt[NQKV * Cd];
__device__ float  g_bqkv[NQKV];

__device__ __forceinline__ float wsum(float v) {
    #pragma unroll
    for (int m = 16; m > 0; m >>= 1) v += __shfl_xor_sync(0xffffffffu, v, m);
    return v;
}

// ============================================================================
// Weight conversion: transpose + fp16
// ============================================================================
__global__ void convert_weights(const float* __restrict__ W1, const float* __restrict__ W2,
                                const float* __restrict__ Wp, const float* __restrict__ Wk,
                                const float* __restrict__ Wv, const float* __restrict__ bp,
                                const float* __restrict__ bk, const float* __restrict__ bv)
{
    int i = blockIdx.x * 256 + threadIdx.x;      // 0 .. 1048575
    {
        int n = i >> 9, k = i & 511;             // W1t [2048 x 512]
        g_w1t[i] = __float2half_rn(W1[k * FFd + n]);
    }
    {
        int n = i >> 11, k = i & 2047;           // W2t [512 x 2048]
        g_w2t[i] = __float2half_rn(W2[k * Cd + n]);
    }
    if (i < NQKV * Cd) {                          // Wqkvt [1536 x 512]
        int n = i >> 9, k = i & 511;
        float v;
        if (n < 512)       v = Wp[(n >> 6) * (Cd * HSd) + k * HSd + (n & 63)];
        else if (n < 1024) { int m = n - 512;  v = Wk[(m >> 6) * (Cd * HSd) + k * HSd + (m & 63)]; }
        else               { int m = n - 1024; v = Wv[(m >> 6) * (Cd * HSd) + k * HSd + (m & 63)]; }
        g_wqkvt[i] = __float2half_rn(v);
    }
    if (i < NQKV) {
        float v;
        if (i < 512)       v = bp[i];
        else if (i < 1024) v = bk[i - 512];
        else               v = bv[i - 1024];
        g_bqkv[i] = v;
    }
}

// ============================================================================
// LN1: one warp per row; write x̂ as fp16
// ============================================================================
__global__ void __launch_bounds__(256)
ln1_kernel(const float* __restrict__ gidx,
           const float* __restrict__ lg1, const float* __restrict__ lb1)
{
    const long long row = (long long)blockIdx.x * 8 + (threadIdx.x >> 5);
    const int lane = threadIdx.x & 31;
    const float* xr = gidx + row * Cd;
    float s1 = 0.f, s2 = 0.f;
    #pragma unroll
    for (int c = lane; c < Cd; c += 32) { float v = xr[c]; s1 += v; s2 += v * v; }
    s1 = wsum(s1); s2 = wsum(s2);
    float mean = s1 * (1.0f / Cd);
    float var  = s2 * (1.0f / Cd) - mean * mean;
    float rstd = rsqrtf(var + 1e-5f);
    #pragma unroll
    for (int c = lane; c < Cd; c += 32) {
        float v = (xr[c] - mean) * rstd * lg1[c] + lb1[c];
        g_xn[row * Cd + c] = __float2half_rn(v);
    }
}

// ============================================================================
// Attention + LN2: block = one batch (8 warps = 8 heads, then 8 tokens)
// ============================================================================
#define AT_PKV_B   (8 * NQKV * 2)                       // 24576
#define AT_SATT_B  AT_PKV_B
#define AT_SXR_B   (AT_SATT_B + 8 * Cd * 4)
#define AT_SW_B    (AT_SXR_B + 8 * Cd * 4)
#define AT_SMEM    (AT_SW_B + 8 * 64 * 4)               // 59392

__global__ void __launch_bounds__(256, 3)
attn_kernel(const float* __restrict__ gidx,
            const float* __restrict__ lg2, const float* __restrict__ lb2)
{
    extern __shared__ char smc[];
    __half* spkv = (__half*)smc;
    float*  satt = (float*)(smc + AT_SATT_B);
    float*  sxr  = (float*)(smc + AT_SXR_B);
    float*  swei = (float*)(smc + AT_SW_B);

    const int tid  = threadIdx.x;
    const int lane = tid & 31;
    const int w    = tid >> 5;
    const long long b = blockIdx.x;

    {
        const uint4* src = (const uint4*)(g_pkv + b * 8 * NQKV);
        uint4* dst = (uint4*)spkv;
        #pragma unroll
        for (int i = 0; i < 6; i++) dst[tid + 256 * i] = src[tid + 256 * i];
        const float4* xs = (const float4*)(gidx + b * 8 * Cd);
        float4* xd = (float4*)sxr;
        #pragma unroll
        for (int i = 0; i < 4; i++) xd[tid + 256 * i] = xs[tid + 256 * i];
    }
    __syncthreads();

    {
        const int h = w;
        #pragma unroll
        for (int hf = 0; hf < 2; hf++) {
            int idx = lane + hf * 32;
            int t = idx >> 3, s = idx & 7;
            const __half2* pr = (const __half2*)(spkv + t * NQKV + h * HSd);
            const __half2* kr = (const __half2*)(spkv + s * NQKV + 512 + h * HSd);
            float acc = 0.f;
            #pragma unroll
            for (int i = 0; i < 32; i++) {
                float2 a = __half22float2(pr[i]);
                float2 c = __half22float2(kr[i]);
                acc += a.x * c.x + a.y * c.y;
            }
            float logit = acc * 0.125f;
            bool valid  = (s <= t);
            float ml = valid ? logit : -3.0e38f;
            float mx = ml;
            mx = fmaxf(mx, __shfl_xor_sync(0xffffffffu, mx, 1));
            mx = fmaxf(mx, __shfl_xor_sync(0xffffffffu, mx, 2));
            mx = fmaxf(mx, __shfl_xor_sync(0xffffffffu, mx, 4));
            float e = valid ? __expf(logit - mx) : 0.f;
            float smv = e;
            smv += __shfl_xor_sync(0xffffffffu, smv, 1);
            smv += __shfl_xor_sync(0xffffffffu, smv, 2);
            smv += __shfl_xor_sync(0xffffffffu, smv, 4);
            swei[w * 64 + idx] = e / smv;
        }
        __syncwarp();
        const int d0 = lane, d1 = lane + 32;
        #pragma unroll
        for (int t = 0; t < 8; t++) {
            float a0 = 0.f, a1 = 0.f;
            #pragma unroll
            for (int s = 0; s < 8; s++) {
                float wv = swei[w * 64 + t * 8 + s];
                const __half* vr = spkv + s * NQKV + 1024 + h * HSd;
                a0 += wv * __half2float(vr[d0]);
                a1 += wv * __half2float(vr[d1]);
            }
            satt[t * Cd + h * HSd + d0] = a0;
            satt[t * Cd + h * HSd + d1] = a1;
        }
    }
    __syncthreads();

    {
        const int t = w;
        const float* ar = satt + t * Cd;
        const float* xr = sxr + t * Cd;
        float s1 = 0.f, s2 = 0.f;
        #pragma unroll
        for (int c = lane; c < Cd; c += 32) { float v = ar[c] + xr[c]; s1 += v; s2 += v * v; }
        s1 = wsum(s1); s2 = wsum(s2);
        float mean = s1 * (1.0f / Cd);
        float var  = s2 * (1.0f / Cd) - mean * mean;
        float rstd = rsqrtf(var + 1e-5f);
        const long long row = b * 8 + t;
        #pragma unroll
        for (int c = lane; c < Cd; c += 32) {
            float v = (ar[c] + xr[c] - mean) * rstd * lg2[c] + lb2[c];
            g_h[row * Cd + c] = __float2half_rn(v);
        }
    }
}

// ============================================================================
// HMMA fp16 GEMM, 3-stage cp.async ring, N-major grid (x = N tile, y = M tile).
// smem stage: A | B  (2 x 10240 B), 3 stages.
// epi 0: FFN1  A=g_h,  B=w1t,   relu(d+bias) -> fp16 g_a
// epi 1: FFN2  A=g_a,  B=w2t,   d+bias+resid -> Of (fp32)
// epi 2: QKV   A=g_xn, B=wqkvt, d+g_bqkv     -> fp16 g_pkv
// ============================================================================

#define KC 32
#define SROW 40
#define MATB (128 * SROW * 2)
#define GSTAGE (2 * MATB)         // 20480
#define G_SMEM (3 * GSTAGE)       // 61440

__device__ __forceinline__ uint32_t smem_u32(const void* p) {
    uint32_t a;
    asm("{ .reg .u64 t; cvta.to.shared.u64 t, %1; cvt.u32.u64 %0, t; }" : "=r"(a) : "l"(p));
    return a;
}
__device__ __forceinline__ void cp16(uint32_t dst, const void* src) {
    asm volatile("cp.async.cg.shared.global [%0], [%1], 16;" :: "r"(dst), "l"(src));
}
__device__ __forceinline__ void cp_commit() {
    asm volatile("cp.async.commit_group;" ::: "memory");
}
__device__ __forceinline__ void cp_wait2() {
    asm volatile("cp.async.wait_group 2;" ::: "memory");
}
__device__ __forceinline__ void ldm_x4(uint32_t* r, uint32_t addr) {
    asm volatile("ldmatrix.sync.aligned.m8n8.x4.shared.b16 {%0,%1,%2,%3}, [%4];"
                 : "=r"(r[0]), "=r"(r[1]), "=r"(r[2]), "=r"(r[3]) : "r"(addr));
}
__device__ __forceinline__ void mma16816(float* c, const uint32_t* a, const uint32_t* b) {
    asm volatile("mma.sync.aligned.m16n8k16.row.col.f32.f16.f16.f32 "
                 "{%0,%1,%2,%3}, {%4,%5,%6,%7}, {%8,%9}, {%0,%1,%2,%3};"
                 : "+f"(c[0]), "+f"(c[1]), "+f"(c[2]), "+f"(c[3])
                 : "r"(a[0]), "r"(a[1]), "r"(a[2]), "r"(a[3]), "r"(b[0]), "r"(b[1]));
}

__global__ void __launch_bounds__(256, 2)
gemm_kernel(const float* __restrict__ bias, const float* __restrict__ resid,
            float* __restrict__ Of, int K, int NTOT, int epi)
{
    extern __shared__ char gsm[];
    const uint32_t sbase = smem_u32(gsm);
    const int tid  = threadIdx.x;
    const int lane = tid & 31;
    const int wid  = tid >> 5;
    const int wm   = wid >> 1;
    const int wn   = wid & 1;
    const int nbase = blockIdx.x * 128;                 // N tile (fast-varying)
    const long long mbase = (long long)blockIdx.y * 128; // M tile
    const int NC = K / KC;

    const __half *A, *B;
    if (epi == 0)      { A = g_h;  B = g_w1t; }
    else if (epi == 1) { A = g_a;  B = g_w2t; }
    else               { A = g_xn; B = g_wqkvt; }

    float acc[2][8][4];
    #pragma unroll
    for (int mi = 0; mi < 2; mi++)
        #pragma unroll
        for (int j = 0; j < 8; j++)
            #pragma unroll
            for (int v = 0; v < 4; v++) acc[mi][j][v] = 0.f;

    const int lrow = tid >> 2, lo16 = (tid & 3) * 16, lk8 = (tid & 3) * 8;
    #define LOAD_CHUNK_ASYNC(kb, soff) do {                                     \
        uint32_t _sb = sbase + (soff);                                          \
        long long ga = (mbase + lrow) * (long long)K + (kb) + lk8;              \
        long long gb = (long long)(nbase + lrow) * K + (kb) + lk8;              \
        uint32_t so = lrow * (SROW * 2) + lo16;                                 \
        cp16(_sb + so,        A + ga);                                          \
        cp16(_sb + MATB + so, B + gb);                                          \
        long long ga2 = (mbase + 64 + lrow) * (long long)K + (kb) + lk8;        \
        long long gb2 = (long long)(nbase + 64 + lrow) * K + (kb) + lk8;        \
        uint32_t so2 = (64 + lrow) * (SROW * 2) + lo16;                         \
        cp16(_sb + so2,        A + ga2);                                        \
        cp16(_sb + MATB + so2, B + gb2);                                        \
    } while (0)

    // prologue: chunks 0 and 1 in flight (NC >= 2 always: K is 512 or 2048)
    LOAD_CHUNK_ASYNC(0, 0);
    cp_commit();
    LOAD_CHUNK_ASYNC(KC, GSTAGE);
    cp_commit();

    const int arow = lane & 15;
    const int asel = (lane >> 4) << 3;
    const int br   = lane & 7;
    const int bsel = (lane >> 3) & 3;
    const int bno  = br + ((bsel >> 1) << 3);
    const int bko  = (bsel & 1) << 3;

    for (int c = 0; c < NC; c++) {
        if (c + 2 < NC) LOAD_CHUNK_ASYNC((c + 2) * KC, ((c + 2) % 3) * GSTAGE);
        cp_commit();                 // uniform one group per iteration
        cp_wait2();                  // oldest (chunk c) complete
        __syncthreads();

        const uint32_t sb = sbase + (c % 3) * GSTAGE;
        #pragma unroll
        for (int ks = 0; ks < 2; ks++) {
            uint32_t a[2][4];
            const int acol = ks * 16 + asel;
            #pragma unroll
            for (int mi = 0; mi < 2; mi++) {
                uint32_t aoff = ((wm * 32 + mi * 16 + arow) * SROW + acol) * 2;
                ldm_x4(a[mi], sb + aoff);
            }
            #pragma unroll
            for (int jj = 0; jj < 4; jj++) {
                uint32_t bb[4];
                uint32_t boff = ((wn * 64 + jj * 16 + bno) * SROW + ks * 16 + bko) * 2;
                ldm_x4(bb, sb + MATB + boff);
                #pragma unroll
                for (int mi = 0; mi < 2; mi++) {
                    mma16816(acc[mi][2 * jj],     a[mi], bb);
                    mma16816(acc[mi][2 * jj + 1], a[mi], bb + 2);
                }
            }
        }
        __syncthreads();             // protect stage reuse by next-iteration loads
    }

    // ---- epilogue ----
    const int r0 = wm * 32 + (lane >> 2);
    const int cn = wn * 64 + ((lane & 3) << 1);
    #pragma unroll
    for (int mi = 0; mi < 2; mi++) {
        #pragma unroll
        for (int j = 0; j < 8; j++) {
            int col = nbase + cn + j * 8;
            long long rg0 = mbase + r0 + mi * 16;
            long long rg1 = rg0 + 8;
            float* d = acc[mi][j];
            if (epi == 0) {
                float b0 = bias[col], b1 = bias[col + 1];
                float v00 = fmaxf(d[0] + b0, 0.f), v01 = fmaxf(d[1] + b1, 0.f);
                float v10 = fmaxf(d[2] + b0, 0.f), v11 = fmaxf(d[3] + b1, 0.f);
                *(__half2*)(g_a + rg0 * NTOT + col) = __floats2half2_rn(v00, v01);
                *(__half2*)(g_a + rg1 * NTOT + col) = __floats2half2_rn(v10, v11);
            } else if (epi == 1) {
                float b0 = bias[col], b1 = bias[col + 1];
                const float2 rv0 = *(const float2*)(resid + rg0 * NTOT + col);
                const float2 rv1 = *(const float2*)(resid + rg1 * NTOT + col);
                *(float2*)(Of + rg0 * NTOT + col) = make_float2(d[0] + b0 + rv0.x, d[1] + b1 + rv0.y);
                *(float2*)(Of + rg1 * NTOT + col) = make_float2(d[2] + b0 + rv1.x, d[3] + b1 + rv1.y);
            } else {
                float b0 = g_bqkv[col], b1 = g_bqkv[col + 1];
                *(__half2*)(g_pkv + rg0 * NTOT + col) = __floats2half2_rn(d[0] + b0, d[1] + b1);
                *(__half2*)(g_pkv + rg1 * NTOT + col) = __floats2half2_rn(d[2] + b0, d[3] + b1);
            }
        }
    }
}

// ============================================================================
// launch
// ============================================================================
extern "C" void kernel_launch(void* const* d_in, const int* in_sizes, int n_in,
                              void* d_out, int out_size)
{
    (void)in_sizes; (void)n_in; (void)out_size;
    const float* gidx = (const float*)d_in[0];
    const float* lg1  = (const float*)d_in[1];
    const float* lb1  = (const float*)d_in[2];
    const float* lg2  = (const float*)d_in[3];
    const float* lb2  = (const float*)d_in[4];
    const float* Wp   = (const float*)d_in[5];
    const float* bp   = (const float*)d_in[6];
    const float* Wk   = (const float*)d_in[7];
    const float* bk   = (const float*)d_in[8];
    const float* Wv   = (const float*)d_in[9];
    const float* bv   = (const float*)d_in[10];
    const float* W1   = (const float*)d_in[11];
    const float* b1f  = (const float*)d_in[12];
    const float* W2   = (const float*)d_in[13];
    const float* b2f  = (const float*)d_in[14];
    float* out = (float*)d_out;

    cudaFuncSetAttribute(gemm_kernel, cudaFuncAttributeMaxDynamicSharedMemorySize, G_SMEM);
    cudaFuncSetAttribute(attn_kernel, cudaFuncAttributeMaxDynamicSharedMemorySize, AT_SMEM);

    convert_weights<<<4096, 256>>>(W1, W2, Wp, Wk, Wv, bp, bk, bv);
    ln1_kernel<<<MTOT / 8, 256>>>(gidx, lg1, lb1);
    // QKV: grid (N tiles, M tiles) — N fast-varying for L2 A-reuse
    gemm_kernel<<<dim3(NQKV / 128, MTOT / 128), 256, G_SMEM>>>(nullptr, nullptr, nullptr, Cd, NQKV, 2);
    attn_kernel<<<MTOT / 8, 256, AT_SMEM>>>(gidx, lg2, lb2);
    // FFN1: relu -> g_a (fp16)
    gemm_kernel<<<dim3(FFd / 128, MTOT / 128), 256, G_SMEM>>>(b1f, nullptr, nullptr, Cd, FFd, 0);
    // FFN2: + b2 + idx -> out
    gemm_kernel<<<dim3(Cd / 128, MTOT / 128), 256, G_SMEM>>>(b2f, gidx, out, FFd, Cd, 1);
}